// round 15
// baseline (speedup 1.0000x reference)
#include <cuda_runtime.h>
#include <cuda_fp16.h>
#include <math.h>
#include <stdint.h>

#define QN      16384
#define CCH     256
#define NCAM    6
#define HFT     32
#define WFT     88
#define DDP     64
#define BEVH    128
#define BEVW    128
#define PTOT    (BEVH*BEVW)
#define KTOT    2304          // 9 taps * 256 ci

// ---------------- scratch (device globals; no allocation allowed) ----------
__device__ __align__(16) __half g_feat_t[NCAM*HFT*WFT*CCH]; // feat fp16 [cam][y][x][c]
__device__ __align__(16) __half g_xh[(size_t)PTOT*CCH];  // agg fp16 (quantized X), [p][ci]
__device__ __align__(16) __half g_wh[(size_t)CCH*KTOT];  // W fp16, [co][tap*256+ci]
__device__ __align__(16) __half g_yh[(size_t)CCH*PTOT];  // conv+bn+relu output fp16, (C,P)
__device__ float g_s[CCH];                     // per-channel spatial SUM (atomic)
__device__ float g_gate[CCH];                  // SE gate (written by last conv block)
__device__ float g_amap[2*PTOT];               // CBAM [max, mean] maps
__device__ int   g_cnt;                        // conv block completion counter

// ---------------- helpers ----------------
__device__ __forceinline__ float sigmoidf(float x) { return 1.f / (1.f + expf(-x)); }

__device__ __forceinline__ uint32_t smem_u32(const void* p) {
    uint32_t a;
    asm("{ .reg .u64 t; cvta.to.shared.u64 t, %1; cvt.u32.u64 %0, t; }" : "=r"(a) : "l"(p));
    return a;
}
__device__ __forceinline__ void cp16(uint32_t dst, const void* src, int sz) {
    asm volatile("cp.async.cg.shared.global [%0], [%1], 16, %2;"
                 :: "r"(dst), "l"(src), "r"(sz) : "memory");
}
__device__ __forceinline__ void ldmx4(uint32_t* r, uint32_t addr) {
    asm volatile("ldmatrix.sync.aligned.m8n8.x4.shared.b16 {%0,%1,%2,%3}, [%4];"
                 : "=r"(r[0]), "=r"(r[1]), "=r"(r[2]), "=r"(r[3]) : "r"(addr));
}
__device__ __forceinline__ void mma16816(float* c, const uint32_t* a, const uint32_t* b) {
    asm volatile("mma.sync.aligned.m16n8k16.row.col.f32.f16.f16.f32 "
                 "{%0,%1,%2,%3}, {%4,%5,%6,%7}, {%8,%9}, {%0,%1,%2,%3};"
                 : "+f"(c[0]), "+f"(c[1]), "+f"(c[2]), "+f"(c[3])
                 : "r"(a[0]), "r"(a[1]), "r"(a[2]), "r"(a[3]), "r"(b[0]), "r"(b[1]));
}

// ---------------- K0: fused prep: feat transpose->fp16 + W->fp16 + zeroing -
#define FEAT_BLOCKS (NCAM*HFT*8)              // 1536
#define WT_BLOCKS   ((CCH*KTOT+255)/256)      // 2304
__global__ void k_prep(const float* __restrict__ feat, const float* __restrict__ conv_w) {
    __shared__ float sm[32][89];
    int b = blockIdx.x;
    int t = threadIdx.x;
    if (b < FEAT_BLOCKS) {
        int cblk = b & 7;
        int y = (b >> 3) & 31;
        int cam = b >> 8;
        for (int idx = t; idx < 32 * WFT; idx += 256) {
            int cc = idx / WFT, x = idx % WFT;
            sm[cc][x] = feat[((size_t)(cam * CCH + cblk * 32 + cc) * HFT + y) * WFT + x];
        }
        __syncthreads();
        for (int idx = t; idx < 32 * WFT; idx += 256) {
            int x = idx / 32, cc = idx % 32;
            g_feat_t[((size_t)(cam * HFT + y) * WFT + x) * CCH + cblk * 32 + cc] =
                __float2half(sm[cc][x]);
        }
    } else {
        int wb = b - FEAT_BLOCKS;
        if (wb == 0) {
            g_s[t] = 0.f;
            if (t == 0) g_cnt = 0;
        }
        int i = wb * 256 + t;
        if (i < CCH * KTOT) {
            int co = i / KTOT;
            int rem = i % KTOT;
            int tap = rem >> 8;
            int ci = rem & 255;
            g_wh[i] = __float2half(conv_w[((size_t)co * CCH + ci) * 9 + tap]);
        }
    }
}

// ---------------- K1: fused query projections + bilinear aggregation -------
__global__ void __launch_bounds__(256) k_qagg(
        const float* __restrict__ bevq, const float* __restrict__ bevp,
        const float* __restrict__ refp, const float* __restrict__ pc,
        const float* __restrict__ l2i, const float* __restrict__ dprob,
        const float* __restrict__ w_pos, const float* __restrict__ b_pos,
        const float* __restrict__ w_img, const float* __restrict__ b_img,
        const float* __restrict__ w_att, const float* __restrict__ b_att,
        float* __restrict__ rp_out) {
    __shared__ int   s_off[48][4];
    __shared__ float s_cw[48][4];
    __shared__ int   s_act[48];

    const int t = threadIdx.x;
    const int wid = t >> 5, lane = t & 31;
    const int q0 = blockIdx.x * 8;
    const int q = q0 + wid;

    // ---- phase 1: per-query projections (warp per query) ----
    {
        const float* bq = bevq + (size_t)q * CCH;
        const float* bp = bevp + (size_t)q * CCH;
        float accP = 0.f;
        float accA[6] = {0.f, 0.f, 0.f, 0.f, 0.f, 0.f};
        float accI[12] = {0.f};
#pragma unroll
        for (int k = 0; k < 8; k++) {
            int ch = lane + k * 32;
            float qv = bq[ch] + bp[ch];
            accP += qv * w_pos[ch];
#pragma unroll
            for (int n = 0; n < 6; n++) accA[n] += qv * w_att[ch * 6 + n];
#pragma unroll
            for (int j = 0; j < 12; j++) accI[j] += qv * w_img[ch * 12 + j];
        }
#pragma unroll
        for (int m = 16; m >= 1; m >>= 1) {
            accP += __shfl_xor_sync(0xffffffffu, accP, m);
#pragma unroll
            for (int n = 0; n < 6; n++) accA[n] += __shfl_xor_sync(0xffffffffu, accA[n], m);
#pragma unroll
            for (int j = 0; j < 12; j++) accI[j] += __shfl_xor_sync(0xffffffffu, accI[j], m);
        }

        float refx = refp[q * 3 + 0];
        float refy = refp[q * 3 + 1];
        float refz = refp[q * 3 + 2];
        float posoff = accP + b_pos[0];
        float xc = fminf(fmaxf(refz, 0.f), 1.f);
        float inv = logf(fmaxf(xc, 1e-5f) / fmaxf(1.f - xc, 1e-5f));
        float z = sigmoidf(inv + posoff);

        if (lane == 0) {
            rp_out[q * 3 + 0] = refx;
            rp_out[q * 3 + 1] = refy;
            rp_out[q * 3 + 2] = z;
        }
        if (lane < 6) {
            int n = lane;
            float sa = sigmoidf(accA[n] + b_att[n]);
            float offx = (accI[2 * n] + b_img[2 * n]) / (float)WFT;
            float offy = (accI[2 * n + 1] + b_img[2 * n + 1]) / (float)HFT;

            float px3 = refx * (pc[3] - pc[0]) + pc[0];
            float py3 = refy * (pc[4] - pc[1]) + pc[1];
            float pz3 = z * (pc[5] - pc[2]) + pc[2];

            const float* M = l2i + n * 16;
            float cx = M[0] * px3 + M[1] * py3 + M[2] * pz3 + M[3];
            float cy = M[4] * px3 + M[5] * py3 + M[6] * pz3 + M[7];
            float d  = M[8] * px3 + M[9] * py3 + M[10] * pz3 + M[11];

            bool mask = d > 1e-5f;
            float dz = fmaxf(d, 1e-5f);
            float gx = (cx / dz / 704.f - 0.5f) * 2.f;
            float gy = (cy / dz / 256.f - 0.5f) * 2.f;
            mask = mask && (gx > -1.f) && (gx < 1.f) && (gy > -1.f) && (gy < 1.f);
            float rd = (d / (float)DDP - 0.5f) * 2.f;
            mask = mask && (rd > -1.f) && (rd < 1.f);

            gx += offx;
            gy += offy;
            float pxf = (gx + 1.f) * 0.5f * (float)WFT - 0.5f;
            float pyf = (gy + 1.f) * 0.5f * (float)HFT - 0.5f;

            float wgt = 0.f;
            if (mask) {
                float pzf = (rd + 1.f) * 0.5f * (float)DDP - 0.5f;
                float fxq = floorf(pxf), fyq = floorf(pyf), fzq = floorf(pzf);
                float wx = pxf - fxq, wy = pyf - fyq, wz = pzf - fzq;
                int x0 = (int)fxq, y0 = (int)fyq, z0 = (int)fzq;
                float dp = 0.f;
#pragma unroll
                for (int dc = 0; dc < 2; dc++)
#pragma unroll
                    for (int yc = 0; yc < 2; yc++)
#pragma unroll
                        for (int xcn = 0; xcn < 2; xcn++) {
                            int xi = x0 + xcn, yi = y0 + yc, zi = z0 + dc;
                            if (xi >= 0 && xi < WFT && yi >= 0 && yi < HFT && zi >= 0 && zi < DDP) {
                                float cw = (xcn ? wx : 1.f - wx) * (yc ? wy : 1.f - wy) * (dc ? wz : 1.f - wz);
                                dp += cw * dprob[((size_t)(n * DDP + zi) * HFT + yi) * WFT + xi];
                            }
                        }
                wgt = sa * dp;
            }

            int e = wid * 6 + n;
            s_act[e] = (wgt != 0.f);
            float fx = floorf(pxf), fy = floorf(pyf);
            float wx = pxf - fx, wy = pyf - fy;
            int x0 = (int)fx, y0 = (int)fy;
            int nbase = n * HFT * WFT;
#pragma unroll
            for (int k = 0; k < 4; k++) {
                int ix = x0 + (k & 1), iy = y0 + (k >> 1);
                bool v = (ix >= 0) && (ix < WFT) && (iy >= 0) && (iy < HFT);
                float cw = ((k & 1) ? wx : 1.f - wx) * ((k >> 1) ? wy : 1.f - wy);
                s_off[e][k] = v ? (nbase + iy * WFT + ix) * CCH : 0;
                s_cw[e][k] = v ? wgt * cw : 0.f;
            }
        }
    }
    __syncthreads();

    // ---- phase 2: channel-octet gather (uint4 = 8 halves per load) --------
    // thread = (q, octet): lanes of a warp cover one q's 256 channels (512B).
    const int qi = t >> 5;               // 0..7 query in block
    const int oct = t & 31;              // channel octet, c0 = oct*8
    float acc[8];
#pragma unroll
    for (int j = 0; j < 8; j++) acc[j] = 0.f;

#pragma unroll
    for (int n = 0; n < 6; n++) {
        int e = qi * 6 + n;
        if (s_act[e]) {
#pragma unroll
            for (int k = 0; k < 4; k++) {
                uint4 v = *(const uint4*)(g_feat_t + s_off[e][k] + oct * 8);
                const __half2* hp = (const __half2*)&v;
                float cw = s_cw[e][k];
#pragma unroll
                for (int j = 0; j < 4; j++) {
                    float2 f2 = __half22float2(hp[j]);
                    acc[2 * j]     = fmaf(cw, f2.x, acc[2 * j]);
                    acc[2 * j + 1] = fmaf(cw, f2.y, acc[2 * j + 1]);
                }
            }
        }
    }
    __half2 o[4];
#pragma unroll
    for (int j = 0; j < 4; j++)
        o[j] = __float22half2_rn(make_float2(acc[2 * j], acc[2 * j + 1]));
    *(uint4*)(g_xh + (size_t)(q0 + qi) * CCH + oct * 8) = *(const uint4*)o;
}

// ---------------- K3: HMMA fp16 conv + fused SE-gate in last block ---------
#define WTILE_B  10240u                       // W tile: 128 rows x 80 B
#define XTILE_B  20480u                       // X tile: 256 rows x 80 B
#define BUF_B    (WTILE_B + XTILE_B)          // 30720
#define CONV_SMEM (3u*BUF_B)                  // 92160 B
__global__ void __launch_bounds__(256, 1) k_conv_mma(
        const float* __restrict__ conv_b, const float* __restrict__ bng,
        const float* __restrict__ bnb, const float* __restrict__ bnm,
        const float* __restrict__ bnv,
        const float* __restrict__ se_w, const float* __restrict__ se_b) {
    extern __shared__ __half s_buf[];
    __shared__ int s_last;
    __shared__ float s_sv[256];

    const int t = threadIdx.x;
    const int lane = t & 31;
    const int wid = t >> 5;
    const int cot = blockIdx.x;           // 0..1 : co half
    const int y0 = blockIdx.y * 2;        // BEV row pair
    const int warp_m = wid & 1, warp_n = wid >> 1;
    const int cm = warp_m * 64, pn = warp_n * 64;

    const uint32_t base0 = smem_u32(s_buf);

    const uint32_t offA = (uint32_t)((lane & 15) * 80 + ((lane >> 4) & 1) * 16);
    const uint32_t offB = (uint32_t)(((lane & 7) + ((lane >> 4) & 1) * 8) * 80 +
                                     ((lane >> 3) & 1) * 16);

    float acc[4][8][4];
#pragma unroll
    for (int mt = 0; mt < 4; mt++)
#pragma unroll
        for (int g = 0; g < 8; g++)
#pragma unroll
            for (int r = 0; r < 4; r++) acc[mt][g][r] = 0.f;

    auto stage = [&](int it, uint32_t sb) {
        const int tap = it >> 3, ci0 = (it & 7) * 32;
        const int dy = tap / 3 - 1, dx = tap % 3 - 1;
        {   // X
            int n = t;
            int gy = y0 + (n >> 7) + dy;
            int gx = (n & 127) + dx;
            bool ok = ((unsigned)gy < 128u) && ((unsigned)gx < 128u);
            size_t xoff = ok ? ((size_t)(gy * 128 + gx) * CCH + ci0) : (size_t)ci0;
            uint32_t xb = sb + WTILE_B + (uint32_t)n * 80;
#pragma unroll
            for (int j = 0; j < 4; j++)
                cp16(xb + j * 16, g_xh + xoff + j * 8, ok ? 16 : 0);
        }
        {   // W
            int r = t & 127, h = t >> 7;
            size_t woff = (size_t)(cot * 128 + r) * KTOT + tap * 256 + ci0;
            uint32_t wb = sb + (uint32_t)r * 80;
#pragma unroll
            for (int j = 0; j < 2; j++) {
                int ch = h * 2 + j;
                cp16(wb + ch * 16, g_wh + woff + ch * 8, 16);
            }
        }
    };

    stage(0, base0);
    asm volatile("cp.async.commit_group;" ::: "memory");
    stage(1, base0 + BUF_B);
    asm volatile("cp.async.commit_group;" ::: "memory");

    int buf = 0;
    for (int it = 0; it < 72; it++) {
        asm volatile("cp.async.wait_group 1;" ::: "memory");
        __syncthreads();

        const uint32_t sb = base0 + (uint32_t)buf * BUF_B;
        const uint32_t wsb = sb;
        const uint32_t xsb = sb + WTILE_B;

        int nbuf = buf + 2; if (nbuf >= 3) nbuf -= 3;
        if (it + 2 < 72) stage(it + 2, base0 + (uint32_t)nbuf * BUF_B);
        asm volatile("cp.async.commit_group;" ::: "memory");

#pragma unroll
        for (int k16 = 0; k16 < 2; k16++) {
            uint32_t A[4][4];
#pragma unroll
            for (int mt = 0; mt < 4; mt++)
                ldmx4(A[mt], wsb + (uint32_t)(cm + mt * 16) * 80 + k16 * 32 + offA);
            uint32_t Bf[4][4];
#pragma unroll
            for (int nt = 0; nt < 4; nt++)
                ldmx4(Bf[nt], xsb + (uint32_t)(pn + nt * 16) * 80 + k16 * 32 + offB);
#pragma unroll
            for (int mt = 0; mt < 4; mt++)
#pragma unroll
                for (int g = 0; g < 8; g++)
                    mma16816(acc[mt][g], A[mt], &Bf[g >> 1][(g & 1) * 2]);
        }

        if (++buf == 3) buf = 0;
    }

    // epilogue: bias + BN + ReLU, write g_yh fp16 (C,P); accumulate SE sums
    const int row = lane >> 2, col = (lane & 3) * 2;
    const int yrow = y0 + (pn >> 7);
    const int xbase = (pn & 127) + col;
#pragma unroll
    for (int mt = 0; mt < 4; mt++) {
#pragma unroll
        for (int h2 = 0; h2 < 2; h2++) {
            int co = cot * 128 + cm + mt * 16 + row + h2 * 8;
            float scale = bng[co] * rsqrtf(bnv[co] + 1e-5f);
            float shift = (conv_b[co] - bnm[co]) * scale + bnb[co];
            __half* yb = &g_yh[(size_t)co * PTOT + yrow * BEVW];
            float csum = 0.f;
#pragma unroll
            for (int g = 0; g < 8; g++) {
                int x = xbase + g * 8;
                float2 v;
                v.x = fmaxf(fmaf(acc[mt][g][h2 * 2 + 0], scale, shift), 0.f);
                v.y = fmaxf(fmaf(acc[mt][g][h2 * 2 + 1], scale, shift), 0.f);
                *(__half2*)&yb[x] = __float22half2_rn(v);
                csum += v.x + v.y;
            }
            csum += __shfl_xor_sync(0xffffffffu, csum, 1);
            csum += __shfl_xor_sync(0xffffffffu, csum, 2);
            if ((lane & 3) == 0) atomicAdd(&g_s[co], csum);
        }
    }

    // ---- last-block SE gate (threadfence reduction pattern) ----
    __threadfence();
    __syncthreads();
    if (t == 0) s_last = (atomicAdd(&g_cnt, 1) == 2 * 64 - 1);
    __syncthreads();
    if (s_last) {
        s_sv[t] = g_s[t] * (1.f / (float)PTOT);
        __syncthreads();
#pragma unroll 4
        for (int i = 0; i < 32; i++) {
            int co = wid * 32 + i;
            const float* wr = se_w + (size_t)co * 256;
            float a = 0.f;
#pragma unroll
            for (int k = 0; k < 256; k += 32)
                a += s_sv[k + lane] * wr[k + lane];
#pragma unroll
            for (int m = 16; m >= 1; m >>= 1)
                a += __shfl_xor_sync(0xffffffffu, a, m);
            if (lane == 0) g_gate[co] = sigmoidf(a + se_b[co]);
        }
    }
}

// ---------------- K5: CBAM max/mean maps (256 blocks, 4-way channel split) -
__global__ void __launch_bounds__(256) k_amap() {
    __shared__ float gs[256];
    __shared__ float red_max[4][64];
    __shared__ float red_sum[4][64];
    int t = threadIdx.x;
    gs[t] = g_gate[t];
    __syncthreads();

    int tq = t & 63;                     // pixel in tile
    int tc = t >> 6;                     // channel quarter
    int p = blockIdx.x * 64 + tq;
    float vmax = -INFINITY, vsum = 0.f;
    int c0 = tc * 64;
#pragma unroll 4
    for (int c = c0; c < c0 + 64; c++) {
        float v = __half2float(g_yh[(size_t)c * PTOT + p]) * gs[c];
        vmax = fmaxf(vmax, v);
        vsum += v;
    }
    red_max[tc][tq] = vmax;
    red_sum[tc][tq] = vsum;
    __syncthreads();
    if (tc == 0) {
        float m = fmaxf(fmaxf(red_max[0][tq], red_max[1][tq]),
                        fmaxf(red_max[2][tq], red_max[3][tq]));
        float s = red_sum[0][tq] + red_sum[1][tq] + red_sum[2][tq] + red_sum[3][tq];
        g_amap[p] = m;
        g_amap[PTOT + p] = s * (1.f / 256.f);
    }
}

// ---------------- K7: fused CBAM 7x7 + gated transpose to (Q,C) ------------
__global__ void k_out(float* __restrict__ out,
                      const float* __restrict__ cw, const float* __restrict__ cb) {
    __shared__ float sm[32][33];
    __shared__ float s_catt[32];
    int q0 = blockIdx.x * 32, c0 = blockIdx.y * 32;
    int tx = threadIdx.x, ty = threadIdx.y;
    int tid = ty * 32 + tx;

    if (tid < 32) {
        int p = q0 + tid;
        int y = p >> 7, x = p & 127;
        float a = 0.f;
#pragma unroll
        for (int ch = 0; ch < 2; ch++)
            for (int ky = 0; ky < 7; ky++)
                for (int kx = 0; kx < 7; kx++) {
                    int yy = y + ky - 3, xx = x + kx - 3;
                    if (yy >= 0 && yy < BEVH && xx >= 0 && xx < BEVW)
                        a += cw[(ch * 7 + ky) * 7 + kx] * g_amap[ch * PTOT + yy * BEVW + xx];
                }
        s_catt[tid] = sigmoidf(a + cb[0]);
    }

#pragma unroll
    for (int j = 0; j < 32; j += 8) {
        int c = c0 + ty + j;
        sm[ty + j][tx] = __half2float(g_yh[(size_t)c * PTOT + q0 + tx]) * g_gate[c];
    }
    __syncthreads();
#pragma unroll
    for (int j = 0; j < 32; j += 8) {
        int q = q0 + ty + j;
        out[(size_t)q * 256 + c0 + tx] = sm[tx][ty + j] * s_catt[ty + j];
    }
}

// ---------------- launch ----------------
extern "C" void kernel_launch(void* const* d_in, const int* in_sizes, int n_in,
                              void* d_out, int out_size) {
    const float* feat   = (const float*)d_in[0];
    const float* bevq   = (const float*)d_in[1];
    const float* bevp   = (const float*)d_in[2];
    const float* refp   = (const float*)d_in[3];
    const float* pc     = (const float*)d_in[4];
    const float* l2i    = (const float*)d_in[5];
    const float* dprob  = (const float*)d_in[6];
    const float* w_pos  = (const float*)d_in[7];
    const float* b_pos  = (const float*)d_in[8];
    const float* w_img  = (const float*)d_in[9];
    const float* b_img  = (const float*)d_in[10];
    const float* w_att  = (const float*)d_in[11];
    const float* b_att  = (const float*)d_in[12];
    const float* conv_w = (const float*)d_in[13];
    const float* conv_b = (const float*)d_in[14];
    const float* bng    = (const float*)d_in[15];
    const float* bnb    = (const float*)d_in[16];
    const float* bnm    = (const float*)d_in[17];
    const float* bnv    = (const float*)d_in[18];
    const float* se_w   = (const float*)d_in[19];
    const float* se_b   = (const float*)d_in[20];
    const float* cbam_w = (const float*)d_in[21];
    const float* cbam_b = (const float*)d_in[22];

    float* out = (float*)d_out;                 // (1, Q, 256)
    float* rp_out = out + (size_t)QN * CCH;     // (1, 1, Q, 3)

    cudaFuncSetAttribute(k_conv_mma, cudaFuncAttributeMaxDynamicSharedMemorySize,
                         CONV_SMEM);

    k_prep<<<FEAT_BLOCKS + WT_BLOCKS, 256>>>(feat, conv_w);
    k_qagg<<<QN / 8, 256>>>(bevq, bevp, refp, pc, l2i, dprob,
                            w_pos, b_pos, w_img, b_img, w_att, b_att, rp_out);
    k_conv_mma<<<dim3(2, 64), 256, CONV_SMEM>>>(conv_b, bng, bnb, bnm, bnv, se_w, se_b);
    k_amap<<<PTOT / 64, 256>>>();
    k_out<<<dim3(PTOT / 32, CCH / 32), dim3(32, 8)>>>(out, cbam_w, cbam_b);
}

// round 16
// speedup vs baseline: 1.1039x; 1.1039x over previous
#include <cuda_runtime.h>
#include <cuda_fp16.h>
#include <math.h>
#include <stdint.h>

#define QN      16384
#define CCH     256
#define NCAM    6
#define HFT     32
#define WFT     88
#define DDP     64
#define BEVH    128
#define BEVW    128
#define PTOT    (BEVH*BEVW)
#define KTOT    2304          // 9 taps * 256 ci

// ---------------- scratch (device globals; no allocation allowed) ----------
__device__ __align__(16) __half g_feat_t[NCAM*HFT*WFT*CCH]; // feat fp16 [cam][y][x][c]
__device__ __align__(16) __half g_xh[(size_t)PTOT*CCH];  // agg fp16 (quantized X), [p][ci]
__device__ __align__(16) __half g_wh[(size_t)CCH*KTOT];  // W fp16, [co][tap*256+ci]
__device__ __align__(16) __half g_yh[(size_t)CCH*PTOT];  // conv+bn+relu output fp16, (C,P)
__device__ float g_s[CCH];                     // per-channel spatial SUM (atomic)
__device__ float g_gate[CCH];                  // SE gate
__device__ float g_amap[2*PTOT];               // CBAM [max, mean] maps

// ---------------- helpers ----------------
__device__ __forceinline__ float sigmoidf(float x) { return 1.f / (1.f + expf(-x)); }

__device__ __forceinline__ uint32_t smem_u32(const void* p) {
    uint32_t a;
    asm("{ .reg .u64 t; cvta.to.shared.u64 t, %1; cvt.u32.u64 %0, t; }" : "=r"(a) : "l"(p));
    return a;
}
__device__ __forceinline__ void cp16(uint32_t dst, const void* src, int sz) {
    asm volatile("cp.async.cg.shared.global [%0], [%1], 16, %2;"
                 :: "r"(dst), "l"(src), "r"(sz) : "memory");
}
__device__ __forceinline__ void ldmx4(uint32_t* r, uint32_t addr) {
    asm volatile("ldmatrix.sync.aligned.m8n8.x4.shared.b16 {%0,%1,%2,%3}, [%4];"
                 : "=r"(r[0]), "=r"(r[1]), "=r"(r[2]), "=r"(r[3]) : "r"(addr));
}
__device__ __forceinline__ void mma16816(float* c, const uint32_t* a, const uint32_t* b) {
    asm volatile("mma.sync.aligned.m16n8k16.row.col.f32.f16.f16.f32 "
                 "{%0,%1,%2,%3}, {%4,%5,%6,%7}, {%8,%9}, {%0,%1,%2,%3};"
                 : "+f"(c[0]), "+f"(c[1]), "+f"(c[2]), "+f"(c[3])
                 : "r"(a[0]), "r"(a[1]), "r"(a[2]), "r"(a[3]), "r"(b[0]), "r"(b[1]));
}

// ---------------- K0: fused prep: feat transpose->fp16 + W->fp16 + zero g_s
#define FEAT_BLOCKS (NCAM*HFT*8)              // 1536
#define WT_BLOCKS   ((CCH*KTOT+255)/256)      // 2304
__global__ void k_prep(const float* __restrict__ feat, const float* __restrict__ conv_w) {
    __shared__ float sm[32][89];
    int b = blockIdx.x;
    int t = threadIdx.x;
    if (b < FEAT_BLOCKS) {
        int cblk = b & 7;
        int y = (b >> 3) & 31;
        int cam = b >> 8;
        for (int idx = t; idx < 32 * WFT; idx += 256) {
            int cc = idx / WFT, x = idx % WFT;
            sm[cc][x] = feat[((size_t)(cam * CCH + cblk * 32 + cc) * HFT + y) * WFT + x];
        }
        __syncthreads();
        for (int idx = t; idx < 32 * WFT; idx += 256) {
            int x = idx / 32, cc = idx % 32;
            g_feat_t[((size_t)(cam * HFT + y) * WFT + x) * CCH + cblk * 32 + cc] =
                __float2half(sm[cc][x]);
        }
    } else {
        int wb = b - FEAT_BLOCKS;
        if (wb == 0) g_s[t] = 0.f;
        int i = wb * 256 + t;
        if (i < CCH * KTOT) {
            int co = i / KTOT;
            int rem = i % KTOT;
            int tap = rem >> 8;
            int ci = rem & 255;
            g_wh[i] = __float2half(conv_w[((size_t)co * CCH + ci) * 9 + tap]);
        }
    }
}

// ---------------- K1: fused query projections + bilinear aggregation -------
__global__ void __launch_bounds__(256) k_qagg(
        const float* __restrict__ bevq, const float* __restrict__ bevp,
        const float* __restrict__ refp, const float* __restrict__ pc,
        const float* __restrict__ l2i, const float* __restrict__ dprob,
        const float* __restrict__ w_pos, const float* __restrict__ b_pos,
        const float* __restrict__ w_img, const float* __restrict__ b_img,
        const float* __restrict__ w_att, const float* __restrict__ b_att,
        float* __restrict__ rp_out) {
    __shared__ int   s_off[48][4];
    __shared__ float s_cw[48][4];
    __shared__ int   s_act[48];

    const int t = threadIdx.x;
    const int wid = t >> 5, lane = t & 31;
    const int q0 = blockIdx.x * 8;
    const int q = q0 + wid;

    // ---- phase 1: per-query projections (warp per query) ----
    {
        const float* bq = bevq + (size_t)q * CCH;
        const float* bp = bevp + (size_t)q * CCH;
        float accP = 0.f;
        float accA[6] = {0.f, 0.f, 0.f, 0.f, 0.f, 0.f};
        float accI[12] = {0.f};
#pragma unroll
        for (int k = 0; k < 8; k++) {
            int ch = lane + k * 32;
            float qv = bq[ch] + bp[ch];
            accP += qv * w_pos[ch];
#pragma unroll
            for (int n = 0; n < 6; n++) accA[n] += qv * w_att[ch * 6 + n];
#pragma unroll
            for (int j = 0; j < 12; j++) accI[j] += qv * w_img[ch * 12 + j];
        }
#pragma unroll
        for (int m = 16; m >= 1; m >>= 1) {
            accP += __shfl_xor_sync(0xffffffffu, accP, m);
#pragma unroll
            for (int n = 0; n < 6; n++) accA[n] += __shfl_xor_sync(0xffffffffu, accA[n], m);
#pragma unroll
            for (int j = 0; j < 12; j++) accI[j] += __shfl_xor_sync(0xffffffffu, accI[j], m);
        }

        float refx = refp[q * 3 + 0];
        float refy = refp[q * 3 + 1];
        float refz = refp[q * 3 + 2];
        float posoff = accP + b_pos[0];
        float xc = fminf(fmaxf(refz, 0.f), 1.f);
        float inv = logf(fmaxf(xc, 1e-5f) / fmaxf(1.f - xc, 1e-5f));
        float z = sigmoidf(inv + posoff);

        if (lane == 0) {
            rp_out[q * 3 + 0] = refx;
            rp_out[q * 3 + 1] = refy;
            rp_out[q * 3 + 2] = z;
        }
        if (lane < 6) {
            int n = lane;
            float sa = sigmoidf(accA[n] + b_att[n]);
            float offx = (accI[2 * n] + b_img[2 * n]) / (float)WFT;
            float offy = (accI[2 * n + 1] + b_img[2 * n + 1]) / (float)HFT;

            float px3 = refx * (pc[3] - pc[0]) + pc[0];
            float py3 = refy * (pc[4] - pc[1]) + pc[1];
            float pz3 = z * (pc[5] - pc[2]) + pc[2];

            const float* M = l2i + n * 16;
            float cx = M[0] * px3 + M[1] * py3 + M[2] * pz3 + M[3];
            float cy = M[4] * px3 + M[5] * py3 + M[6] * pz3 + M[7];
            float d  = M[8] * px3 + M[9] * py3 + M[10] * pz3 + M[11];

            bool mask = d > 1e-5f;
            float dz = fmaxf(d, 1e-5f);
            float gx = (cx / dz / 704.f - 0.5f) * 2.f;
            float gy = (cy / dz / 256.f - 0.5f) * 2.f;
            mask = mask && (gx > -1.f) && (gx < 1.f) && (gy > -1.f) && (gy < 1.f);
            float rd = (d / (float)DDP - 0.5f) * 2.f;
            mask = mask && (rd > -1.f) && (rd < 1.f);

            gx += offx;
            gy += offy;
            float pxf = (gx + 1.f) * 0.5f * (float)WFT - 0.5f;
            float pyf = (gy + 1.f) * 0.5f * (float)HFT - 0.5f;

            float wgt = 0.f;
            if (mask) {
                float pzf = (rd + 1.f) * 0.5f * (float)DDP - 0.5f;
                float fxq = floorf(pxf), fyq = floorf(pyf), fzq = floorf(pzf);
                float wx = pxf - fxq, wy = pyf - fyq, wz = pzf - fzq;
                int x0 = (int)fxq, y0 = (int)fyq, z0 = (int)fzq;
                float dp = 0.f;
#pragma unroll
                for (int dc = 0; dc < 2; dc++)
#pragma unroll
                    for (int yc = 0; yc < 2; yc++)
#pragma unroll
                        for (int xcn = 0; xcn < 2; xcn++) {
                            int xi = x0 + xcn, yi = y0 + yc, zi = z0 + dc;
                            if (xi >= 0 && xi < WFT && yi >= 0 && yi < HFT && zi >= 0 && zi < DDP) {
                                float cw = (xcn ? wx : 1.f - wx) * (yc ? wy : 1.f - wy) * (dc ? wz : 1.f - wz);
                                dp += cw * dprob[((size_t)(n * DDP + zi) * HFT + yi) * WFT + xi];
                            }
                        }
                wgt = sa * dp;
            }

            int e = wid * 6 + n;
            s_act[e] = (wgt != 0.f);
            float fx = floorf(pxf), fy = floorf(pyf);
            float wx = pxf - fx, wy = pyf - fy;
            int x0 = (int)fx, y0 = (int)fy;
            int nbase = n * HFT * WFT;
#pragma unroll
            for (int k = 0; k < 4; k++) {
                int ix = x0 + (k & 1), iy = y0 + (k >> 1);
                bool v = (ix >= 0) && (ix < WFT) && (iy >= 0) && (iy < HFT);
                float cw = ((k & 1) ? wx : 1.f - wx) * ((k >> 1) ? wy : 1.f - wy);
                s_off[e][k] = v ? (nbase + iy * WFT + ix) * CCH : 0;
                s_cw[e][k] = v ? wgt * cw : 0.f;
            }
        }
    }
    __syncthreads();

    // ---- phase 2: channel-octet gather (uint4 = 8 halves per load) --------
    const int qi = t >> 5;               // 0..7 query in block
    const int oct = t & 31;              // channel octet, c0 = oct*8
    float acc[8];
#pragma unroll
    for (int j = 0; j < 8; j++) acc[j] = 0.f;

#pragma unroll
    for (int n = 0; n < 6; n++) {
        int e = qi * 6 + n;
        if (s_act[e]) {
#pragma unroll
            for (int k = 0; k < 4; k++) {
                uint4 v = *(const uint4*)(g_feat_t + s_off[e][k] + oct * 8);
                const __half2* hp = (const __half2*)&v;
                float cw = s_cw[e][k];
#pragma unroll
                for (int j = 0; j < 4; j++) {
                    float2 f2 = __half22float2(hp[j]);
                    acc[2 * j]     = fmaf(cw, f2.x, acc[2 * j]);
                    acc[2 * j + 1] = fmaf(cw, f2.y, acc[2 * j + 1]);
                }
            }
        }
    }
    __half2 o[4];
#pragma unroll
    for (int j = 0; j < 4; j++)
        o[j] = __float22half2_rn(make_float2(acc[2 * j], acc[2 * j + 1]));
    *(uint4*)(g_xh + (size_t)(q0 + qi) * CCH + oct * 8) = *(const uint4*)o;
}

// ---------------- K3: HMMA fp16 conv, 64x64 warp tiles, triple buffer ------
#define WTILE_B  10240u                       // W tile: 128 rows x 80 B
#define XTILE_B  20480u                       // X tile: 256 rows x 80 B
#define BUF_B    (WTILE_B + XTILE_B)          // 30720
#define CONV_SMEM (3u*BUF_B)                  // 92160 B
__global__ void __launch_bounds__(256, 1) k_conv_mma(
        const float* __restrict__ conv_b, const float* __restrict__ bng,
        const float* __restrict__ bnb, const float* __restrict__ bnm,
        const float* __restrict__ bnv) {
    extern __shared__ __half s_buf[];

    const int t = threadIdx.x;
    const int lane = t & 31;
    const int wid = t >> 5;
    const int cot = blockIdx.x;           // 0..1 : co half
    const int y0 = blockIdx.y * 2;        // BEV row pair
    const int warp_m = wid & 1, warp_n = wid >> 1;
    const int cm = warp_m * 64, pn = warp_n * 64;

    const uint32_t base0 = smem_u32(s_buf);

    const uint32_t offA = (uint32_t)((lane & 15) * 80 + ((lane >> 4) & 1) * 16);
    const uint32_t offB = (uint32_t)(((lane & 7) + ((lane >> 4) & 1) * 8) * 80 +
                                     ((lane >> 3) & 1) * 16);

    float acc[4][8][4];
#pragma unroll
    for (int mt = 0; mt < 4; mt++)
#pragma unroll
        for (int g = 0; g < 8; g++)
#pragma unroll
            for (int r = 0; r < 4; r++) acc[mt][g][r] = 0.f;

    auto stage = [&](int it, uint32_t sb) {
        const int tap = it >> 3, ci0 = (it & 7) * 32;
        const int dy = tap / 3 - 1, dx = tap % 3 - 1;
        {   // X
            int n = t;
            int gy = y0 + (n >> 7) + dy;
            int gx = (n & 127) + dx;
            bool ok = ((unsigned)gy < 128u) && ((unsigned)gx < 128u);
            size_t xoff = ok ? ((size_t)(gy * 128 + gx) * CCH + ci0) : (size_t)ci0;
            uint32_t xb = sb + WTILE_B + (uint32_t)n * 80;
#pragma unroll
            for (int j = 0; j < 4; j++)
                cp16(xb + j * 16, g_xh + xoff + j * 8, ok ? 16 : 0);
        }
        {   // W
            int r = t & 127, h = t >> 7;
            size_t woff = (size_t)(cot * 128 + r) * KTOT + tap * 256 + ci0;
            uint32_t wb = sb + (uint32_t)r * 80;
#pragma unroll
            for (int j = 0; j < 2; j++) {
                int ch = h * 2 + j;
                cp16(wb + ch * 16, g_wh + woff + ch * 8, 16);
            }
        }
    };

    stage(0, base0);
    asm volatile("cp.async.commit_group;" ::: "memory");
    stage(1, base0 + BUF_B);
    asm volatile("cp.async.commit_group;" ::: "memory");

    int buf = 0;
    for (int it = 0; it < 72; it++) {
        asm volatile("cp.async.wait_group 1;" ::: "memory");
        __syncthreads();

        const uint32_t sb = base0 + (uint32_t)buf * BUF_B;
        const uint32_t wsb = sb;
        const uint32_t xsb = sb + WTILE_B;

        int nbuf = buf + 2; if (nbuf >= 3) nbuf -= 3;
        if (it + 2 < 72) stage(it + 2, base0 + (uint32_t)nbuf * BUF_B);
        asm volatile("cp.async.commit_group;" ::: "memory");

#pragma unroll
        for (int k16 = 0; k16 < 2; k16++) {
            uint32_t A[4][4];
#pragma unroll
            for (int mt = 0; mt < 4; mt++)
                ldmx4(A[mt], wsb + (uint32_t)(cm + mt * 16) * 80 + k16 * 32 + offA);
            uint32_t Bf[4][4];
#pragma unroll
            for (int nt = 0; nt < 4; nt++)
                ldmx4(Bf[nt], xsb + (uint32_t)(pn + nt * 16) * 80 + k16 * 32 + offB);
#pragma unroll
            for (int mt = 0; mt < 4; mt++)
#pragma unroll
                for (int g = 0; g < 8; g++)
                    mma16816(acc[mt][g], A[mt], &Bf[g >> 1][(g & 1) * 2]);
        }

        if (++buf == 3) buf = 0;
    }

    // epilogue: bias + BN + ReLU, write g_yh fp16 (C,P); accumulate SE sums
    const int row = lane >> 2, col = (lane & 3) * 2;
    const int yrow = y0 + (pn >> 7);
    const int xbase = (pn & 127) + col;
#pragma unroll
    for (int mt = 0; mt < 4; mt++) {
#pragma unroll
        for (int h2 = 0; h2 < 2; h2++) {
            int co = cot * 128 + cm + mt * 16 + row + h2 * 8;
            float scale = bng[co] * rsqrtf(bnv[co] + 1e-5f);
            float shift = (conv_b[co] - bnm[co]) * scale + bnb[co];
            __half* yb = &g_yh[(size_t)co * PTOT + yrow * BEVW];
            float csum = 0.f;
#pragma unroll
            for (int g = 0; g < 8; g++) {
                int x = xbase + g * 8;
                float2 v;
                v.x = fmaxf(fmaf(acc[mt][g][h2 * 2 + 0], scale, shift), 0.f);
                v.y = fmaxf(fmaf(acc[mt][g][h2 * 2 + 1], scale, shift), 0.f);
                *(__half2*)&yb[x] = __float22half2_rn(v);
                csum += v.x + v.y;
            }
            csum += __shfl_xor_sync(0xffffffffu, csum, 1);
            csum += __shfl_xor_sync(0xffffffffu, csum, 2);
            if ((lane & 3) == 0) atomicAdd(&g_s[co], csum);
        }
    }
}

// ---------------- K4: SE gate, parallel (32 blocks x 8 warps, warp/output) -
__global__ void k_gate(const float* __restrict__ se_w, const float* __restrict__ se_b) {
    __shared__ float sv[256];
    int t = threadIdx.x;
    int wid = t >> 5, lane = t & 31;
    sv[t] = g_s[t] * (1.f / (float)PTOT);
    __syncthreads();
    int co = blockIdx.x * 8 + wid;
    const float* wr = se_w + (size_t)co * 256;
    float a = 0.f;
#pragma unroll
    for (int k = 0; k < 256; k += 32)
        a += sv[k + lane] * wr[k + lane];
#pragma unroll
    for (int m = 16; m >= 1; m >>= 1)
        a += __shfl_xor_sync(0xffffffffu, a, m);
    if (lane == 0) g_gate[co] = sigmoidf(a + se_b[co]);
}

// ---------------- K5: CBAM max/mean maps (512 blocks, 8-way channel split) -
__global__ void __launch_bounds__(256) k_amap() {
    __shared__ float gs[256];
    __shared__ float red_max[8][32];
    __shared__ float red_sum[8][32];
    int t = threadIdx.x;
    gs[t] = g_gate[t];
    __syncthreads();

    int tq = t & 31;                     // pixel in tile
    int tc = t >> 5;                     // channel eighth
    int p = blockIdx.x * 32 + tq;
    float vmax = -INFINITY, vsum = 0.f;
    int c0 = tc * 32;
#pragma unroll 4
    for (int c = c0; c < c0 + 32; c++) {
        float v = __half2float(g_yh[(size_t)c * PTOT + p]) * gs[c];
        vmax = fmaxf(vmax, v);
        vsum += v;
    }
    red_max[tc][tq] = vmax;
    red_sum[tc][tq] = vsum;
    __syncthreads();
    if (tc == 0) {
        float m = vmax, s = vsum;
#pragma unroll
        for (int j = 1; j < 8; j++) {
            m = fmaxf(m, red_max[j][tq]);
            s += red_sum[j][tq];
        }
        g_amap[p] = m;
        g_amap[PTOT + p] = s * (1.f / 256.f);
    }
}

// ---------------- K7: fused CBAM 7x7 + gated transpose to (Q,C) ------------
__global__ void k_out(float* __restrict__ out,
                      const float* __restrict__ cw, const float* __restrict__ cb) {
    __shared__ float sm[32][33];
    __shared__ float s_catt[32];
    int q0 = blockIdx.x * 32, c0 = blockIdx.y * 32;
    int tx = threadIdx.x, ty = threadIdx.y;
    int tid = ty * 32 + tx;

    if (tid < 32) {
        int p = q0 + tid;
        int y = p >> 7, x = p & 127;
        float a = 0.f;
#pragma unroll
        for (int ch = 0; ch < 2; ch++)
            for (int ky = 0; ky < 7; ky++)
                for (int kx = 0; kx < 7; kx++) {
                    int yy = y + ky - 3, xx = x + kx - 3;
                    if (yy >= 0 && yy < BEVH && xx >= 0 && xx < BEVW)
                        a += cw[(ch * 7 + ky) * 7 + kx] * g_amap[ch * PTOT + yy * BEVW + xx];
                }
        s_catt[tid] = sigmoidf(a + cb[0]);
    }

#pragma unroll
    for (int j = 0; j < 32; j += 8) {
        int c = c0 + ty + j;
        sm[ty + j][tx] = __half2float(g_yh[(size_t)c * PTOT + q0 + tx]) * g_gate[c];
    }
    __syncthreads();
#pragma unroll
    for (int j = 0; j < 32; j += 8) {
        int q = q0 + ty + j;
        out[(size_t)q * 256 + c0 + tx] = sm[tx][ty + j] * s_catt[ty + j];
    }
}

// ---------------- launch ----------------
extern "C" void kernel_launch(void* const* d_in, const int* in_sizes, int n_in,
                              void* d_out, int out_size) {
    const float* feat   = (const float*)d_in[0];
    const float* bevq   = (const float*)d_in[1];
    const float* bevp   = (const float*)d_in[2];
    const float* refp   = (const float*)d_in[3];
    const float* pc     = (const float*)d_in[4];
    const float* l2i    = (const float*)d_in[5];
    const float* dprob  = (const float*)d_in[6];
    const float* w_pos  = (const float*)d_in[7];
    const float* b_pos  = (const float*)d_in[8];
    const float* w_img  = (const float*)d_in[9];
    const float* b_img  = (const float*)d_in[10];
    const float* w_att  = (const float*)d_in[11];
    const float* b_att  = (const float*)d_in[12];
    const float* conv_w = (const float*)d_in[13];
    const float* conv_b = (const float*)d_in[14];
    const float* bng    = (const float*)d_in[15];
    const float* bnb    = (const float*)d_in[16];
    const float* bnm    = (const float*)d_in[17];
    const float* bnv    = (const float*)d_in[18];
    const float* se_w   = (const float*)d_in[19];
    const float* se_b   = (const float*)d_in[20];
    const float* cbam_w = (const float*)d_in[21];
    const float* cbam_b = (const float*)d_in[22];

    float* out = (float*)d_out;                 // (1, Q, 256)
    float* rp_out = out + (size_t)QN * CCH;     // (1, 1, Q, 3)

    cudaFuncSetAttribute(k_conv_mma, cudaFuncAttributeMaxDynamicSharedMemorySize,
                         CONV_SMEM);

    k_prep<<<FEAT_BLOCKS + WT_BLOCKS, 256>>>(feat, conv_w);
    k_qagg<<<QN / 8, 256>>>(bevq, bevp, refp, pc, l2i, dprob,
                            w_pos, b_pos, w_img, b_img, w_att, b_att, rp_out);
    k_conv_mma<<<dim3(2, 64), 256, CONV_SMEM>>>(conv_b, bng, bnb, bnm, bnv);
    k_gate<<<32, 256>>>(se_w, se_b);
    k_amap<<<PTOT / 32, 256>>>();
    k_out<<<dim3(PTOT / 32, CCH / 32), dim3(32, 8)>>>(out, cbam_w, cbam_b);
}

// round 17
// speedup vs baseline: 1.2249x; 1.1096x over previous
#include <cuda_runtime.h>
#include <cuda_fp16.h>
#include <math.h>
#include <stdint.h>

#define QN      16384
#define CCH     256
#define NCAM    6
#define HFT     32
#define WFT     88
#define DDP     64
#define BEVH    128
#define BEVW    128
#define PTOT    (BEVH*BEVW)
#define KTOT    2304          // 9 taps * 256 ci

// ---------------- scratch (device globals; no allocation allowed) ----------
__device__ __align__(16) __half g_feat_t[NCAM*HFT*WFT*CCH]; // feat fp16 [cam][y][x][c]
__device__ __align__(16) __half g_xh[(size_t)PTOT*CCH];  // agg fp16 (quantized X), [p][ci]
__device__ __align__(16) __half g_wh[(size_t)CCH*KTOT];  // W fp16, [co][tap*256+ci]
__device__ __align__(16) __half g_yh[(size_t)CCH*PTOT];  // conv+bn+relu output fp16, (C,P)
__device__ float g_s[CCH];                     // per-channel spatial SUM (atomic)
__device__ float g_gate[CCH];                  // SE gate
__device__ float g_amap[2*PTOT];               // CBAM [max, mean] maps

// ---------------- helpers ----------------
__device__ __forceinline__ float sigmoidf(float x) { return 1.f / (1.f + expf(-x)); }

__device__ __forceinline__ uint32_t smem_u32(const void* p) {
    uint32_t a;
    asm("{ .reg .u64 t; cvta.to.shared.u64 t, %1; cvt.u32.u64 %0, t; }" : "=r"(a) : "l"(p));
    return a;
}
__device__ __forceinline__ void cp16(uint32_t dst, const void* src, int sz) {
    asm volatile("cp.async.cg.shared.global [%0], [%1], 16, %2;"
                 :: "r"(dst), "l"(src), "r"(sz) : "memory");
}
__device__ __forceinline__ void ldmx4(uint32_t* r, uint32_t addr) {
    asm volatile("ldmatrix.sync.aligned.m8n8.x4.shared.b16 {%0,%1,%2,%3}, [%4];"
                 : "=r"(r[0]), "=r"(r[1]), "=r"(r[2]), "=r"(r[3]) : "r"(addr));
}
__device__ __forceinline__ void mma16816(float* c, const uint32_t* a, const uint32_t* b) {
    asm volatile("mma.sync.aligned.m16n8k16.row.col.f32.f16.f16.f32 "
                 "{%0,%1,%2,%3}, {%4,%5,%6,%7}, {%8,%9}, {%0,%1,%2,%3};"
                 : "+f"(c[0]), "+f"(c[1]), "+f"(c[2]), "+f"(c[3])
                 : "r"(a[0]), "r"(a[1]), "r"(a[2]), "r"(a[3]), "r"(b[0]), "r"(b[1]));
}

// ---------------- K0: fused prep: feat transpose->fp16 + W->fp16 + zero g_s
// W path: block per 2 co -> fully coalesced conv_w reads, smem transpose
// (stride-9 smem reads are conflict-free: gcd(9,32)=1), coalesced g_wh writes.
#define FEAT_BLOCKS (NCAM*HFT*8)              // 1536
#define WCO_BLOCKS  (CCH/2)                   // 128
__global__ void k_prep(const float* __restrict__ feat, const float* __restrict__ conv_w) {
    __shared__ float sbuf[2 * KTOT];          // 18432 B (>= 32*89 floats)
    int b = blockIdx.x;
    int t = threadIdx.x;
    if (b < FEAT_BLOCKS) {
        float (*sm)[89] = (float(*)[89])sbuf;
        int cblk = b & 7;
        int y = (b >> 3) & 31;
        int cam = b >> 8;
        for (int idx = t; idx < 32 * WFT; idx += 256) {
            int cc = idx / WFT, x = idx % WFT;
            sm[cc][x] = feat[((size_t)(cam * CCH + cblk * 32 + cc) * HFT + y) * WFT + x];
        }
        __syncthreads();
        for (int idx = t; idx < 32 * WFT; idx += 256) {
            int x = idx / 32, cc = idx % 32;
            g_feat_t[((size_t)(cam * HFT + y) * WFT + x) * CCH + cblk * 32 + cc] =
                __float2half(sm[cc][x]);
        }
    } else {
        int wb = b - FEAT_BLOCKS;
        if (wb == 0) g_s[t] = 0.f;
        int co0 = wb * 2;
        const float* src = conv_w + (size_t)co0 * KTOT;
#pragma unroll
        for (int idx = t; idx < 2 * KTOT; idx += 256) sbuf[idx] = src[idx];
        __syncthreads();
#pragma unroll
        for (int idx = t; idx < 2 * KTOT; idx += 256) {
            int co_l = idx / KTOT;
            int rem = idx - co_l * KTOT;
            int tap = rem >> 8;
            int ci = rem & 255;
            g_wh[(size_t)(co0 + co_l) * KTOT + tap * 256 + ci] =
                __float2half(sbuf[co_l * KTOT + ci * 9 + tap]);
        }
    }
}

// ---------------- K1: fused query projections + bilinear aggregation -------
// Projection weights staged in smem, transposed ([n][ch]/[j][ch]) so the
// phase-1 inner loop is conflict-free LDS instead of strided global gathers.
__global__ void __launch_bounds__(256) k_qagg(
        const float* __restrict__ bevq, const float* __restrict__ bevp,
        const float* __restrict__ refp, const float* __restrict__ pc,
        const float* __restrict__ l2i, const float* __restrict__ dprob,
        const float* __restrict__ w_pos, const float* __restrict__ b_pos,
        const float* __restrict__ w_img, const float* __restrict__ b_img,
        const float* __restrict__ w_att, const float* __restrict__ b_att,
        float* __restrict__ rp_out) {
    __shared__ int   s_off[48][4];
    __shared__ float s_cw[48][4];
    __shared__ int   s_act[48];
    __shared__ float s_wpos[256];
    __shared__ float s_watt[6][256];
    __shared__ float s_wimg[12][256];

    const int t = threadIdx.x;
    const int wid = t >> 5, lane = t & 31;
    const int q0 = blockIdx.x * 8;
    const int q = q0 + wid;

    // stage projection weights (transposed; L1-cached source)
    s_wpos[t] = w_pos[t];
#pragma unroll
    for (int i = t; i < 6 * 256; i += 256) {
        int n = i >> 8, ch = i & 255;
        s_watt[n][ch] = w_att[ch * 6 + n];
    }
#pragma unroll
    for (int i = t; i < 12 * 256; i += 256) {
        int j = i >> 8, ch = i & 255;
        s_wimg[j][ch] = w_img[ch * 12 + j];
    }
    __syncthreads();

    // ---- phase 1: per-query projections (warp per query) ----
    {
        const float* bq = bevq + (size_t)q * CCH;
        const float* bp = bevp + (size_t)q * CCH;
        float accP = 0.f;
        float accA[6] = {0.f, 0.f, 0.f, 0.f, 0.f, 0.f};
        float accI[12] = {0.f};
#pragma unroll
        for (int k = 0; k < 8; k++) {
            int ch = lane + k * 32;
            float qv = bq[ch] + bp[ch];
            accP += qv * s_wpos[ch];
#pragma unroll
            for (int n = 0; n < 6; n++) accA[n] += qv * s_watt[n][ch];
#pragma unroll
            for (int j = 0; j < 12; j++) accI[j] += qv * s_wimg[j][ch];
        }
#pragma unroll
        for (int m = 16; m >= 1; m >>= 1) {
            accP += __shfl_xor_sync(0xffffffffu, accP, m);
#pragma unroll
            for (int n = 0; n < 6; n++) accA[n] += __shfl_xor_sync(0xffffffffu, accA[n], m);
#pragma unroll
            for (int j = 0; j < 12; j++) accI[j] += __shfl_xor_sync(0xffffffffu, accI[j], m);
        }

        float refx = refp[q * 3 + 0];
        float refy = refp[q * 3 + 1];
        float refz = refp[q * 3 + 2];
        float posoff = accP + b_pos[0];
        float xc = fminf(fmaxf(refz, 0.f), 1.f);
        float inv = logf(fmaxf(xc, 1e-5f) / fmaxf(1.f - xc, 1e-5f));
        float z = sigmoidf(inv + posoff);

        if (lane == 0) {
            rp_out[q * 3 + 0] = refx;
            rp_out[q * 3 + 1] = refy;
            rp_out[q * 3 + 2] = z;
        }
        if (lane < 6) {
            int n = lane;
            float sa = sigmoidf(accA[n] + b_att[n]);
            float offx = (accI[2 * n] + b_img[2 * n]) / (float)WFT;
            float offy = (accI[2 * n + 1] + b_img[2 * n + 1]) / (float)HFT;

            float px3 = refx * (pc[3] - pc[0]) + pc[0];
            float py3 = refy * (pc[4] - pc[1]) + pc[1];
            float pz3 = z * (pc[5] - pc[2]) + pc[2];

            const float* M = l2i + n * 16;
            float cx = M[0] * px3 + M[1] * py3 + M[2] * pz3 + M[3];
            float cy = M[4] * px3 + M[5] * py3 + M[6] * pz3 + M[7];
            float d  = M[8] * px3 + M[9] * py3 + M[10] * pz3 + M[11];

            bool mask = d > 1e-5f;
            float dz = fmaxf(d, 1e-5f);
            float gx = (cx / dz / 704.f - 0.5f) * 2.f;
            float gy = (cy / dz / 256.f - 0.5f) * 2.f;
            mask = mask && (gx > -1.f) && (gx < 1.f) && (gy > -1.f) && (gy < 1.f);
            float rd = (d / (float)DDP - 0.5f) * 2.f;
            mask = mask && (rd > -1.f) && (rd < 1.f);

            gx += offx;
            gy += offy;
            float pxf = (gx + 1.f) * 0.5f * (float)WFT - 0.5f;
            float pyf = (gy + 1.f) * 0.5f * (float)HFT - 0.5f;

            float wgt = 0.f;
            if (mask) {
                float pzf = (rd + 1.f) * 0.5f * (float)DDP - 0.5f;
                float fxq = floorf(pxf), fyq = floorf(pyf), fzq = floorf(pzf);
                float wx = pxf - fxq, wy = pyf - fyq, wz = pzf - fzq;
                int x0 = (int)fxq, y0 = (int)fyq, z0 = (int)fzq;
                float dp = 0.f;
#pragma unroll
                for (int dc = 0; dc < 2; dc++)
#pragma unroll
                    for (int yc = 0; yc < 2; yc++)
#pragma unroll
                        for (int xcn = 0; xcn < 2; xcn++) {
                            int xi = x0 + xcn, yi = y0 + yc, zi = z0 + dc;
                            if (xi >= 0 && xi < WFT && yi >= 0 && yi < HFT && zi >= 0 && zi < DDP) {
                                float cw = (xcn ? wx : 1.f - wx) * (yc ? wy : 1.f - wy) * (dc ? wz : 1.f - wz);
                                dp += cw * dprob[((size_t)(n * DDP + zi) * HFT + yi) * WFT + xi];
                            }
                        }
                wgt = sa * dp;
            }

            int e = wid * 6 + n;
            s_act[e] = (wgt != 0.f);
            float fx = floorf(pxf), fy = floorf(pyf);
            float wx = pxf - fx, wy = pyf - fy;
            int x0 = (int)fx, y0 = (int)fy;
            int nbase = n * HFT * WFT;
#pragma unroll
            for (int k = 0; k < 4; k++) {
                int ix = x0 + (k & 1), iy = y0 + (k >> 1);
                bool v = (ix >= 0) && (ix < WFT) && (iy >= 0) && (iy < HFT);
                float cw = ((k & 1) ? wx : 1.f - wx) * ((k >> 1) ? wy : 1.f - wy);
                s_off[e][k] = v ? (nbase + iy * WFT + ix) * CCH : 0;
                s_cw[e][k] = v ? wgt * cw : 0.f;
            }
        }
    }
    __syncthreads();

    // ---- phase 2: channel-octet gather (uint4 = 8 halves per load) --------
    const int qi = t >> 5;               // 0..7 query in block
    const int oct = t & 31;              // channel octet, c0 = oct*8
    float acc[8];
#pragma unroll
    for (int j = 0; j < 8; j++) acc[j] = 0.f;

#pragma unroll
    for (int n = 0; n < 6; n++) {
        int e = qi * 6 + n;
        if (s_act[e]) {
#pragma unroll
            for (int k = 0; k < 4; k++) {
                uint4 v = *(const uint4*)(g_feat_t + s_off[e][k] + oct * 8);
                const __half2* hp = (const __half2*)&v;
                float cw = s_cw[e][k];
#pragma unroll
                for (int j = 0; j < 4; j++) {
                    float2 f2 = __half22float2(hp[j]);
                    acc[2 * j]     = fmaf(cw, f2.x, acc[2 * j]);
                    acc[2 * j + 1] = fmaf(cw, f2.y, acc[2 * j + 1]);
                }
            }
        }
    }
    __half2 o[4];
#pragma unroll
    for (int j = 0; j < 4; j++)
        o[j] = __float22half2_rn(make_float2(acc[2 * j], acc[2 * j + 1]));
    *(uint4*)(g_xh + (size_t)(q0 + qi) * CCH + oct * 8) = *(const uint4*)o;
}

// ---------------- K3: HMMA fp16 conv, 64x64 warp tiles, triple buffer ------
#define WTILE_B  10240u                       // W tile: 128 rows x 80 B
#define XTILE_B  20480u                       // X tile: 256 rows x 80 B
#define BUF_B    (WTILE_B + XTILE_B)          // 30720
#define CONV_SMEM (3u*BUF_B)                  // 92160 B
__global__ void __launch_bounds__(256, 1) k_conv_mma(
        const float* __restrict__ conv_b, const float* __restrict__ bng,
        const float* __restrict__ bnb, const float* __restrict__ bnm,
        const float* __restrict__ bnv) {
    extern __shared__ __half s_buf[];

    const int t = threadIdx.x;
    const int lane = t & 31;
    const int wid = t >> 5;
    const int cot = blockIdx.x;           // 0..1 : co half
    const int y0 = blockIdx.y * 2;        // BEV row pair
    const int warp_m = wid & 1, warp_n = wid >> 1;
    const int cm = warp_m * 64, pn = warp_n * 64;

    const uint32_t base0 = smem_u32(s_buf);

    const uint32_t offA = (uint32_t)((lane & 15) * 80 + ((lane >> 4) & 1) * 16);
    const uint32_t offB = (uint32_t)(((lane & 7) + ((lane >> 4) & 1) * 8) * 80 +
                                     ((lane >> 3) & 1) * 16);

    float acc[4][8][4];
#pragma unroll
    for (int mt = 0; mt < 4; mt++)
#pragma unroll
        for (int g = 0; g < 8; g++)
#pragma unroll
            for (int r = 0; r < 4; r++) acc[mt][g][r] = 0.f;

    auto stage = [&](int it, uint32_t sb) {
        const int tap = it >> 3, ci0 = (it & 7) * 32;
        const int dy = tap / 3 - 1, dx = tap % 3 - 1;
        {   // X
            int n = t;
            int gy = y0 + (n >> 7) + dy;
            int gx = (n & 127) + dx;
            bool ok = ((unsigned)gy < 128u) && ((unsigned)gx < 128u);
            size_t xoff = ok ? ((size_t)(gy * 128 + gx) * CCH + ci0) : (size_t)ci0;
            uint32_t xb = sb + WTILE_B + (uint32_t)n * 80;
#pragma unroll
            for (int j = 0; j < 4; j++)
                cp16(xb + j * 16, g_xh + xoff + j * 8, ok ? 16 : 0);
        }
        {   // W
            int r = t & 127, h = t >> 7;
            size_t woff = (size_t)(cot * 128 + r) * KTOT + tap * 256 + ci0;
            uint32_t wb = sb + (uint32_t)r * 80;
#pragma unroll
            for (int j = 0; j < 2; j++) {
                int ch = h * 2 + j;
                cp16(wb + ch * 16, g_wh + woff + ch * 8, 16);
            }
        }
    };

    stage(0, base0);
    asm volatile("cp.async.commit_group;" ::: "memory");
    stage(1, base0 + BUF_B);
    asm volatile("cp.async.commit_group;" ::: "memory");

    int buf = 0;
    for (int it = 0; it < 72; it++) {
        asm volatile("cp.async.wait_group 1;" ::: "memory");
        __syncthreads();

        const uint32_t sb = base0 + (uint32_t)buf * BUF_B;
        const uint32_t wsb = sb;
        const uint32_t xsb = sb + WTILE_B;

        int nbuf = buf + 2; if (nbuf >= 3) nbuf -= 3;
        if (it + 2 < 72) stage(it + 2, base0 + (uint32_t)nbuf * BUF_B);
        asm volatile("cp.async.commit_group;" ::: "memory");

#pragma unroll
        for (int k16 = 0; k16 < 2; k16++) {
            uint32_t A[4][4];
#pragma unroll
            for (int mt = 0; mt < 4; mt++)
                ldmx4(A[mt], wsb + (uint32_t)(cm + mt * 16) * 80 + k16 * 32 + offA);
            uint32_t Bf[4][4];
#pragma unroll
            for (int nt = 0; nt < 4; nt++)
                ldmx4(Bf[nt], xsb + (uint32_t)(pn + nt * 16) * 80 + k16 * 32 + offB);
#pragma unroll
            for (int mt = 0; mt < 4; mt++)
#pragma unroll
                for (int g = 0; g < 8; g++)
                    mma16816(acc[mt][g], A[mt], &Bf[g >> 1][(g & 1) * 2]);
        }

        if (++buf == 3) buf = 0;
    }

    // epilogue: bias + BN + ReLU, write g_yh fp16 (C,P); accumulate SE sums
    const int row = lane >> 2, col = (lane & 3) * 2;
    const int yrow = y0 + (pn >> 7);
    const int xbase = (pn & 127) + col;
#pragma unroll
    for (int mt = 0; mt < 4; mt++) {
#pragma unroll
        for (int h2 = 0; h2 < 2; h2++) {
            int co = cot * 128 + cm + mt * 16 + row + h2 * 8;
            float scale = bng[co] * rsqrtf(bnv[co] + 1e-5f);
            float shift = (conv_b[co] - bnm[co]) * scale + bnb[co];
            __half* yb = &g_yh[(size_t)co * PTOT + yrow * BEVW];
            float csum = 0.f;
#pragma unroll
            for (int g = 0; g < 8; g++) {
                int x = xbase + g * 8;
                float2 v;
                v.x = fmaxf(fmaf(acc[mt][g][h2 * 2 + 0], scale, shift), 0.f);
                v.y = fmaxf(fmaf(acc[mt][g][h2 * 2 + 1], scale, shift), 0.f);
                *(__half2*)&yb[x] = __float22half2_rn(v);
                csum += v.x + v.y;
            }
            csum += __shfl_xor_sync(0xffffffffu, csum, 1);
            csum += __shfl_xor_sync(0xffffffffu, csum, 2);
            if ((lane & 3) == 0) atomicAdd(&g_s[co], csum);
        }
    }
}

// ---------------- K4: SE gate, parallel (32 blocks x 8 warps, warp/output) -
__global__ void k_gate(const float* __restrict__ se_w, const float* __restrict__ se_b) {
    __shared__ float sv[256];
    int t = threadIdx.x;
    int wid = t >> 5, lane = t & 31;
    sv[t] = g_s[t] * (1.f / (float)PTOT);
    __syncthreads();
    int co = blockIdx.x * 8 + wid;
    const float* wr = se_w + (size_t)co * 256;
    float a = 0.f;
#pragma unroll
    for (int k = 0; k < 256; k += 32)
        a += sv[k + lane] * wr[k + lane];
#pragma unroll
    for (int m = 16; m >= 1; m >>= 1)
        a += __shfl_xor_sync(0xffffffffu, a, m);
    if (lane == 0) g_gate[co] = sigmoidf(a + se_b[co]);
}

// ---------------- K5: CBAM max/mean maps (512 blocks, 8-way channel split) -
__global__ void __launch_bounds__(256) k_amap() {
    __shared__ float gs[256];
    __shared__ float red_max[8][32];
    __shared__ float red_sum[8][32];
    int t = threadIdx.x;
    gs[t] = g_gate[t];
    __syncthreads();

    int tq = t & 31;                     // pixel in tile
    int tc = t >> 5;                     // channel eighth
    int p = blockIdx.x * 32 + tq;
    float vmax = -INFINITY, vsum = 0.f;
    int c0 = tc * 32;
#pragma unroll 4
    for (int c = c0; c < c0 + 32; c++) {
        float v = __half2float(g_yh[(size_t)c * PTOT + p]) * gs[c];
        vmax = fmaxf(vmax, v);
        vsum += v;
    }
    red_max[tc][tq] = vmax;
    red_sum[tc][tq] = vsum;
    __syncthreads();
    if (tc == 0) {
        float m = vmax, s = vsum;
#pragma unroll
        for (int j = 1; j < 8; j++) {
            m = fmaxf(m, red_max[j][tq]);
            s += red_sum[j][tq];
        }
        g_amap[p] = m;
        g_amap[PTOT + p] = s * (1.f / 256.f);
    }
}

// ---------------- K7: fused CBAM 7x7 + gated transpose to (Q,C) ------------
__global__ void k_out(float* __restrict__ out,
                      const float* __restrict__ cw, const float* __restrict__ cb) {
    __shared__ float sm[32][33];
    __shared__ float s_catt[32];
    int q0 = blockIdx.x * 32, c0 = blockIdx.y * 32;
    int tx = threadIdx.x, ty = threadIdx.y;
    int tid = ty * 32 + tx;

    if (tid < 32) {
        int p = q0 + tid;
        int y = p >> 7, x = p & 127;
        float a = 0.f;
#pragma unroll
        for (int ch = 0; ch < 2; ch++)
            for (int ky = 0; ky < 7; ky++)
                for (int kx = 0; kx < 7; kx++) {
                    int yy = y + ky - 3, xx = x + kx - 3;
                    if (yy >= 0 && yy < BEVH && xx >= 0 && xx < BEVW)
                        a += cw[(ch * 7 + ky) * 7 + kx] * g_amap[ch * PTOT + yy * BEVW + xx];
                }
        s_catt[tid] = sigmoidf(a + cb[0]);
    }

#pragma unroll
    for (int j = 0; j < 32; j += 8) {
        int c = c0 + ty + j;
        sm[ty + j][tx] = __half2float(g_yh[(size_t)c * PTOT + q0 + tx]) * g_gate[c];
    }
    __syncthreads();
#pragma unroll
    for (int j = 0; j < 32; j += 8) {
        int q = q0 + ty + j;
        out[(size_t)q * 256 + c0 + tx] = sm[tx][ty + j] * s_catt[ty + j];
    }
}

// ---------------- launch ----------------
extern "C" void kernel_launch(void* const* d_in, const int* in_sizes, int n_in,
                              void* d_out, int out_size) {
    const float* feat   = (const float*)d_in[0];
    const float* bevq   = (const float*)d_in[1];
    const float* bevp   = (const float*)d_in[2];
    const float* refp   = (const float*)d_in[3];
    const float* pc     = (const float*)d_in[4];
    const float* l2i    = (const float*)d_in[5];
    const float* dprob  = (const float*)d_in[6];
    const float* w_pos  = (const float*)d_in[7];
    const float* b_pos  = (const float*)d_in[8];
    const float* w_img  = (const float*)d_in[9];
    const float* b_img  = (const float*)d_in[10];
    const float* w_att  = (const float*)d_in[11];
    const float* b_att  = (const float*)d_in[12];
    const float* conv_w = (const float*)d_in[13];
    const float* conv_b = (const float*)d_in[14];
    const float* bng    = (const float*)d_in[15];
    const float* bnb    = (const float*)d_in[16];
    const float* bnm    = (const float*)d_in[17];
    const float* bnv    = (const float*)d_in[18];
    const float* se_w   = (const float*)d_in[19];
    const float* se_b   = (const float*)d_in[20];
    const float* cbam_w = (const float*)d_in[21];
    const float* cbam_b = (const float*)d_in[22];

    float* out = (float*)d_out;                 // (1, Q, 256)
    float* rp_out = out + (size_t)QN * CCH;     // (1, 1, Q, 3)

    cudaFuncSetAttribute(k_conv_mma, cudaFuncAttributeMaxDynamicSharedMemorySize,
                         CONV_SMEM);

    k_prep<<<FEAT_BLOCKS + WCO_BLOCKS, 256>>>(feat, conv_w);
    k_qagg<<<QN / 8, 256>>>(bevq, bevp, refp, pc, l2i, dprob,
                            w_pos, b_pos, w_img, b_img, w_att, b_att, rp_out);
    k_conv_mma<<<dim3(2, 64), 256, CONV_SMEM>>>(conv_b, bng, bnb, bnm, bnv);
    k_gate<<<32, 256>>>(se_w, se_b);
    k_amap<<<PTOT / 32, 256>>>();
    k_out<<<dim3(PTOT / 32, CCH / 32), dim3(32, 8)>>>(out, cbam_w, cbam_b);
}